// round 6
// baseline (speedup 1.0000x reference)
#include <cuda_runtime.h>

#define BB 8
#define HH 1024
#define WW 1024
#define NT 256

// ---- NCC: float2-per-lane warp tasks, register row-ring ----
#define OUTW 56                        // output cols per warp-row
#define NSTRIP 19                      // ceil(1024/56)
#define SEG 32                         // output rows per warp task
#define VSEG (HH / SEG)                // 32
#define NCC_WT (NSTRIP * VSEG * BB)    // 4864
#define NCC_BLOCKS (NCC_WT / 8)        // 608

// ---- smoothness strips ----
#define SM_R 64
#define SM_STRIPS (HH / SM_R)             // 16
#define SM_PLANES (BB * 2)                // 16
#define SM_BLOCKS (SM_PLANES * SM_STRIPS) // 256

#define TOTAL_BLOCKS (NCC_BLOCKS + SM_BLOCKS)  // 864

__device__ double g_acc[3] = {0.0, 0.0, 0.0};   // [0]=cc, [1]=dx, [2]=dy
__device__ unsigned int g_count = 0;

__device__ __forceinline__ float frcp(float x) {
    float r;
    asm("rcp.approx.ftz.f32 %0, %1;" : "=f"(r) : "f"(x));
    return r;
}

// Horizontal 9-tap window sums for a lane owning cols (ca, ca+1).
// wA = sum cols ca-4..ca+4 ; wB = sum cols ca-3..ca+5. Valid for lanes 2..29.
__device__ __forceinline__ void hwin(float va, float vb, float& wA, float& wB) {
    const unsigned m = 0xffffffffu;
    float P   = va + vb;                             // pair l
    float t1  = P + __shfl_down_sync(m, P, 1);       // pairs l,l+1
    float Q   = t1 + __shfl_down_sync(m, t1, 2);     // pairs l..l+3
    float Qm2 = __shfl_up_sync(m, Q, 2);             // cols ca-4..ca+3
    float Qm1 = __shfl_up_sync(m, Q, 1);             // cols ca-2..ca+5
    float ap2 = __shfl_down_sync(m, va, 2);          // col ca+4
    float bm2 = __shfl_up_sync(m, vb, 2);            // col ca-3
    wA = Qm2 + ap2;
    wB = Qm1 + bm2;
}

template<bool MASKED>
__device__ __forceinline__ float ncc_task(const float2* __restrict__ Ip,
                                          const float2* __restrict__ Jp,
                                          int y0, bool okA, bool okB,
                                          bool maskA, bool maskB)
{
    const int RS = WW / 2;
    const float2 z = make_float2(0.f, 0.f);

    float2 rI[8], rJ[8];   // ring: rows y-4..y+3 ; slot = (row-(y0-4)) & 7
    float sIa=0,sIb=0,sJa=0,sJb=0,sIIa=0,sIIb=0,sJJa=0,sJJb=0,sIJa=0,sIJb=0;

    // prefill rows y0-4 .. y0+3
    #pragma unroll
    for (int k = 0; k < 8; k++) {
        const int y = y0 - 4 + k;
        const bool ok = (y >= 0);
        float2 vi = ok ? Ip[(long)y * RS] : z;
        float2 vj = ok ? Jp[(long)y * RS] : z;
        if (MASKED) {
            if (!okA) { vi.x = 0.f; vj.x = 0.f; }
            if (!okB) { vi.y = 0.f; vj.y = 0.f; }
        }
        rI[k] = vi; rJ[k] = vj;
        sIa += vi.x; sIb += vi.y; sJa += vj.x; sJb += vj.y;
        sIIa = fmaf(vi.x, vi.x, sIIa); sIIb = fmaf(vi.y, vi.y, sIIb);
        sJJa = fmaf(vj.x, vj.x, sJJa); sJJb = fmaf(vj.y, vj.y, sJJb);
        sIJa = fmaf(vi.x, vj.x, sIJa); sIJb = fmaf(vi.y, vj.y, sIJb);
    }

    const float2* pIn = Ip + (long)(y0 + 4) * RS;   // row y+4 stream
    const float2* pJn = Jp + (long)(y0 + 4) * RS;
    const int ylim = HH - 4 - y0;                   // iterations with in-range y+4

    const float inv81 = 1.0f / 81.0f;
    float ccSum = 0.f;

    for (int blk = 0; blk < SEG / 8; blk++) {
        #pragma unroll
        for (int k = 0; k < 8; k++) {
            const int u = blk * 8 + k;              // y = y0 + u ; ring slot = k
            const bool okn = u < ylim;
            float2 iN = okn ? pIn[(long)u * RS] : z;
            float2 jN = okn ? pJn[(long)u * RS] : z;
            if (MASKED) {
                if (!okA) { iN.x = 0.f; jN.x = 0.f; }
                if (!okB) { iN.y = 0.f; jN.y = 0.f; }
            }
            const float2 iO = rI[k];   // row y-4 (to drop AFTER compute)
            const float2 jO = rJ[k];
            rI[k] = iN; rJ[k] = jN;    // slot k now holds row y+4

            // add row y+4 -> window rows y-4..y+4
            sIa += iN.x; sIb += iN.y; sJa += jN.x; sJb += jN.y;
            sIIa = fmaf(iN.x, iN.x, sIIa); sIIb = fmaf(iN.y, iN.y, sIIb);
            sJJa = fmaf(jN.x, jN.x, sJJa); sJJb = fmaf(jN.y, jN.y, sJJb);
            sIJa = fmaf(iN.x, jN.x, sIJa); sIJb = fmaf(iN.y, jN.y, sIJb);

            // horizontal 9-tap on the 5 vertical sums
            float TIa,TIb,TJa,TJb,TIIa,TIIb,TJJa,TJJb,TIJa,TIJb;
            hwin(sIa,  sIb,  TIa,  TIb);
            hwin(sJa,  sJb,  TJa,  TJb);
            hwin(sIIa, sIIb, TIIa, TIIb);
            hwin(sJJa, sJJb, TJJa, TJJb);
            hwin(sIJa, sIJb, TIJa, TIJb);

            {   // col A
                float u1 = TIa * inv81;
                float cr = fmaf(-u1, TJa, TIJa);
                float iv = fmaf(-u1, TIa, TIIa);
                float jv = fmaf(-TJa * inv81, TJa, TJJa);
                float cc = cr * cr * frcp(fmaf(iv, jv, 1e-9f));
                if (maskA) ccSum += cc;
            }
            {   // col B
                float u1 = TIb * inv81;
                float cr = fmaf(-u1, TJb, TIJb);
                float iv = fmaf(-u1, TIb, TIIb);
                float jv = fmaf(-TJb * inv81, TJb, TJJb);
                float cc = cr * cr * frcp(fmaf(iv, jv, 1e-9f));
                if (maskB) ccSum += cc;
            }

            // drop row y-4 -> window rows y-3..y+4 (ready for next y)
            sIa -= iO.x; sIb -= iO.y; sJa -= jO.x; sJb -= jO.y;
            sIIa = fmaf(-iO.x, iO.x, sIIa); sIIb = fmaf(-iO.y, iO.y, sIIb);
            sJJa = fmaf(-jO.x, jO.x, sJJa); sJJb = fmaf(-jO.y, jO.y, sJJb);
            sIJa = fmaf(-iO.x, jO.x, sIJa); sIJb = fmaf(-iO.y, jO.y, sIJb);
        }
    }
    return ccSum;
}

__global__ __launch_bounds__(NT)
void fused_kernel(const float* __restrict__ I,
                  const float* __restrict__ J,
                  const float* __restrict__ S,
                  float* __restrict__ out)
{
    __shared__ float red[3][NT / 32];
    const int tid  = threadIdx.x;
    const int bid  = blockIdx.x;
    const int lane = tid & 31;

    float acc0 = 0.f, acc1 = 0.f, acc2 = 0.f;

    if (bid < NCC_BLOCKS) {
        // ---------------- NCC ----------------
        const int w = bid * 8 + (tid >> 5);
        const int s = w % NSTRIP;
        const int r = w / NSTRIP;
        const int v = r % VSEG;
        const int b = r / VSEG;

        const int ca = s * OUTW - 4 + 2 * lane;         // even raw col for this lane
        const bool okA = (unsigned)ca < (unsigned)WW;
        const bool okB = (unsigned)(ca + 1) < (unsigned)WW;
        int cac = ca < 0 ? 0 : (ca > (WW - 2) ? (WW - 2) : ca);

        const float2* Ip = (const float2*)(I + (size_t)b * HH * WW + cac);
        const float2* Jp = (const float2*)(J + (size_t)b * HH * WW + cac);

        const bool lmid  = (lane >= 2) && (lane <= 29);
        const bool maskA = lmid && okA;
        const bool maskB = lmid && okB;
        const int  y0    = v * SEG;

        const bool clean = __all_sync(0xffffffffu, okA && okB);
        acc0 = clean ? ncc_task<false>(Ip, Jp, y0, okA, okB, maskA, maskB)
                     : ncc_task<true >(Ip, Jp, y0, okA, okB, maskA, maskB);
    } else {
        // ---------------- smoothness: row-sliding strip ----------------
        const int sbid  = bid - NCC_BLOCKS;
        const int strip = sbid % SM_STRIPS;
        const int plane = sbid / SM_STRIPS;
        const float*  spf = S + (size_t)plane * HH * WW;
        const float4* sp4 = (const float4*)spf;
        const int y0 = strip * SM_R;

        float dx = 0.f, dy = 0.f;
        float4 cur = sp4[(size_t)y0 * (WW / 4) + tid];

        #pragma unroll 4
        for (int y = y0; y < y0 + SM_R; y++) {
            float d1 = cur.y - cur.x;
            float d2 = cur.z - cur.y;
            float d3 = cur.w - cur.z;
            dx += d1 * d1 + d2 * d2 + d3 * d3;
            if (tid < (WW / 4 - 1)) {
                float nx = spf[(size_t)y * WW + 4 * tid + 4];
                float d4 = nx - cur.w;
                dx += d4 * d4;
            }
            if (y + 1 < HH) {
                float4 nxt = sp4[(size_t)(y + 1) * (WW / 4) + tid];
                float e1 = nxt.x - cur.x;
                float e2 = nxt.y - cur.y;
                float e3 = nxt.z - cur.z;
                float e4 = nxt.w - cur.w;
                dy += e1 * e1 + e2 * e2 + e3 * e3 + e4 * e4;
                cur = nxt;
            }
        }
        acc1 = dx; acc2 = dy;
    }

    // ---------------- block reduction + global accumulate ----------------
    const unsigned full = 0xffffffffu;
    #pragma unroll
    for (int off = 16; off; off >>= 1) {
        acc0 += __shfl_down_sync(full, acc0, off);
        acc1 += __shfl_down_sync(full, acc1, off);
        acc2 += __shfl_down_sync(full, acc2, off);
    }
    if (lane == 0) {
        const int wi = tid >> 5;
        red[0][wi] = acc0;
        red[1][wi] = acc1;
        red[2][wi] = acc2;
    }
    __syncthreads();
    if (tid == 0) {
        float a0 = 0.f, a1 = 0.f, a2 = 0.f;
        #pragma unroll
        for (int wi = 0; wi < NT / 32; wi++) {
            a0 += red[0][wi]; a1 += red[1][wi]; a2 += red[2][wi];
        }
        if (bid < NCC_BLOCKS) {
            atomicAdd(&g_acc[0], (double)a0);
        } else {
            atomicAdd(&g_acc[1], (double)a1);
            atomicAdd(&g_acc[2], (double)a2);
        }
        __threadfence();
        unsigned old = atomicAdd(&g_count, 1u);
        if (old == TOTAL_BLOCKS - 1) {
            __threadfence();
            volatile double* ga = g_acc;
            double c  = ga[0];
            double xs = ga[1];
            double ys = ga[2];
            double nccl = -c / ((double)BB * HH * WW);
            double mdx  = xs / ((double)BB * 2.0 * HH * (WW - 1));
            double mdy  = ys / ((double)BB * 2.0 * (HH - 1) * WW);
            double sml  = (mdx + mdy) * 0.5 * 0.01;
            out[0] = (float)(nccl + sml);
            out[1] = (float)nccl;
            out[2] = (float)sml;
            // reset for next graph replay
            ga[0] = 0.0; ga[1] = 0.0; ga[2] = 0.0;
            __threadfence();
            atomicExch(&g_count, 0u);
        }
    }
}

extern "C" void kernel_launch(void* const* d_in, const int* in_sizes, int n_in,
                              void* d_out, int out_size)
{
    const float* I = (const float*)d_in[0];
    const float* J = (const float*)d_in[1];
    const float* s = (const float*)d_in[2];
    // d_in[3] = sum_filt (all-ones 9x9) is baked into the math
    float* out = (float*)d_out;

    fused_kernel<<<TOTAL_BLOCKS, NT>>>(I, J, s, out);
}

// round 7
// speedup vs baseline: 1.0539x; 1.0539x over previous
#include <cuda_runtime.h>

#define BB 8
#define HH 1024
#define WW 1024
#define NT 256

// ---- NCC: float2-per-lane warp tasks, I-only register row-ring ----
#define OUTW 56                        // output cols per warp-row
#define NSTRIP 19                      // ceil(1024/56)
#define SEG 32                         // output rows per warp task
#define VSEG (HH / SEG)                // 32
#define NCC_WT (NSTRIP * VSEG * BB)    // 4864
#define NCC_BLOCKS (NCC_WT / 8)        // 608

// ---- smoothness strips (scheduled FIRST for wave mixing) ----
#define SM_R 64
#define SM_STRIPS (HH / SM_R)             // 16
#define SM_PLANES (BB * 2)                // 16
#define SM_BLOCKS (SM_PLANES * SM_STRIPS) // 256

#define TOTAL_BLOCKS (SM_BLOCKS + NCC_BLOCKS)  // 864

__device__ double g_acc[3] = {0.0, 0.0, 0.0};   // [0]=cc, [1]=dx, [2]=dy
__device__ unsigned int g_count = 0;

__device__ __forceinline__ float frcp(float x) {
    float r;
    asm("rcp.approx.ftz.f32 %0, %1;" : "=f"(r) : "f"(x));
    return r;
}

// Horizontal 9-tap window sums for a lane owning cols (ca, ca+1).
// wA = sum cols ca-4..ca+4 ; wB = sum cols ca-3..ca+5. Valid for lanes 2..29.
__device__ __forceinline__ void hwin(float va, float vb, float& wA, float& wB) {
    const unsigned m = 0xffffffffu;
    float P   = va + vb;                             // pair l
    float t1  = P + __shfl_down_sync(m, P, 1);       // pairs l,l+1
    float Q   = t1 + __shfl_down_sync(m, t1, 2);     // pairs l..l+3
    float Qm2 = __shfl_up_sync(m, Q, 2);             // cols ca-4..ca+3
    float Qm1 = __shfl_up_sync(m, Q, 1);             // cols ca-2..ca+5
    float ap2 = __shfl_down_sync(m, va, 2);          // col ca+4
    float bm2 = __shfl_up_sync(m, vb, 2);            // col ca-3
    wA = Qm2 + ap2;
    wB = Qm1 + bm2;
}

template<bool MASKED, bool YCLEAN>
__device__ __forceinline__ float ncc_task(const float2* __restrict__ Ip,
                                          const float2* __restrict__ Jp,
                                          int y0, bool okA, bool okB,
                                          bool maskA, bool maskB)
{
    const int RS = WW / 2;
    const float2 z = make_float2(0.f, 0.f);

    float2 rI[8];   // ring of I rows y-4..y+3 ; slot = (row-(y0-4)) & 7
    float sIa=0,sIb=0,sJa=0,sJb=0,sIIa=0,sIIb=0,sJJa=0,sJJb=0,sIJa=0,sIJb=0;

    // prefill rows y0-4 .. y0+3
    #pragma unroll
    for (int k = 0; k < 8; k++) {
        const int y = y0 - 4 + k;
        const bool ok = YCLEAN || (y >= 0);
        float2 vi = ok ? Ip[(long)y * RS] : z;
        float2 vj = ok ? Jp[(long)y * RS] : z;
        if (MASKED) {
            if (!okA) { vi.x = 0.f; vj.x = 0.f; }
            if (!okB) { vi.y = 0.f; vj.y = 0.f; }
        }
        rI[k] = vi;
        sIa += vi.x; sIb += vi.y; sJa += vj.x; sJb += vj.y;
        sIIa = fmaf(vi.x, vi.x, sIIa); sIIb = fmaf(vi.y, vi.y, sIIb);
        sJJa = fmaf(vj.x, vj.x, sJJa); sJJb = fmaf(vj.y, vj.y, sJJb);
        sIJa = fmaf(vi.x, vj.x, sIJa); sIJb = fmaf(vi.y, vj.y, sIJb);
    }

    const float2* pIn = Ip + (long)(y0 + 4) * RS;   // new-row stream (y+4)
    const float2* pJn = Jp + (long)(y0 + 4) * RS;
    const float2* pJo = Jp + (long)(y0 - 4) * RS;   // old-J stream (y-4)
    const int ylim = HH - 4 - y0;

    const float inv81 = 1.0f / 81.0f;
    float ccSum = 0.f;

    for (int blk = 0; blk < SEG / 8; blk++) {
        #pragma unroll
        for (int k = 0; k < 8; k++) {
            const int u = blk * 8 + k;              // y = y0 + u ; ring slot = k
            float2 iN, jN, jO;
            if (YCLEAN) {
                iN = pIn[(long)u * RS];
                jN = pJn[(long)u * RS];
                jO = pJo[(long)u * RS];
            } else {
                const bool okn = u < ylim;
                const bool oko = (y0 + u - 4) >= 0;
                iN = okn ? pIn[(long)u * RS] : z;
                jN = okn ? pJn[(long)u * RS] : z;
                jO = oko ? pJo[(long)u * RS] : z;
            }
            if (MASKED) {
                if (!okA) { iN.x = 0.f; jN.x = 0.f; jO.x = 0.f; }
                if (!okB) { iN.y = 0.f; jN.y = 0.f; jO.y = 0.f; }
            }
            const float2 iO = rI[k];   // I row y-4 (drop AFTER compute)
            rI[k] = iN;

            // add row y+4 -> window rows y-4..y+4
            sIa += iN.x; sIb += iN.y; sJa += jN.x; sJb += jN.y;
            sIIa = fmaf(iN.x, iN.x, sIIa); sIIb = fmaf(iN.y, iN.y, sIIb);
            sJJa = fmaf(jN.x, jN.x, sJJa); sJJb = fmaf(jN.y, jN.y, sJJb);
            sIJa = fmaf(iN.x, jN.x, sIJa); sIJb = fmaf(iN.y, jN.y, sIJb);

            // horizontal 9-tap on the 5 vertical sums
            float TIa,TIb,TJa,TJb,TIIa,TIIb,TJJa,TJJb,TIJa,TIJb;
            hwin(sIa,  sIb,  TIa,  TIb);
            hwin(sJa,  sJb,  TJa,  TJb);
            hwin(sIIa, sIIb, TIIa, TIIb);
            hwin(sJJa, sJJb, TJJa, TJJb);
            hwin(sIJa, sIJb, TIJa, TIJb);

            {   // col A
                float u1 = TIa * inv81;
                float cr = fmaf(-u1, TJa, TIJa);
                float iv = fmaf(-u1, TIa, TIIa);
                float jv = fmaf(-TJa * inv81, TJa, TJJa);
                float cc = cr * cr * frcp(fmaf(iv, jv, 1e-9f));
                if (maskA) ccSum += cc;
            }
            {   // col B
                float u1 = TIb * inv81;
                float cr = fmaf(-u1, TJb, TIJb);
                float iv = fmaf(-u1, TIb, TIIb);
                float jv = fmaf(-TJb * inv81, TJb, TJJb);
                float cc = cr * cr * frcp(fmaf(iv, jv, 1e-9f));
                if (maskB) ccSum += cc;
            }

            // drop row y-4 -> window becomes y-3..y+4 (ready for next y)
            sIa -= iO.x; sIb -= iO.y; sJa -= jO.x; sJb -= jO.y;
            sIIa = fmaf(-iO.x, iO.x, sIIa); sIIb = fmaf(-iO.y, iO.y, sIIb);
            sJJa = fmaf(-jO.x, jO.x, sJJa); sJJb = fmaf(-jO.y, jO.y, sJJb);
            sIJa = fmaf(-iO.x, jO.x, sIJa); sIJb = fmaf(-iO.y, jO.y, sIJb);
        }
    }
    return ccSum;
}

__global__ __launch_bounds__(NT, 4)
void fused_kernel(const float* __restrict__ I,
                  const float* __restrict__ J,
                  const float* __restrict__ S,
                  float* __restrict__ out)
{
    __shared__ float red[3][NT / 32];
    const int tid  = threadIdx.x;
    const int bid  = blockIdx.x;
    const int lane = tid & 31;

    float acc0 = 0.f, acc1 = 0.f, acc2 = 0.f;

    if (bid < SM_BLOCKS) {
        // ---------------- smoothness: row-sliding strip ----------------
        const int strip = bid % SM_STRIPS;
        const int plane = bid / SM_STRIPS;
        const float*  spf = S + (size_t)plane * HH * WW;
        const float4* sp4 = (const float4*)spf;
        const int y0 = strip * SM_R;

        float dx = 0.f, dy = 0.f;
        float4 cur = sp4[(size_t)y0 * (WW / 4) + tid];

        #pragma unroll 4
        for (int y = y0; y < y0 + SM_R; y++) {
            float d1 = cur.y - cur.x;
            float d2 = cur.z - cur.y;
            float d3 = cur.w - cur.z;
            dx += d1 * d1 + d2 * d2 + d3 * d3;
            if (tid < (WW / 4 - 1)) {
                float nx = spf[(size_t)y * WW + 4 * tid + 4];
                float d4 = nx - cur.w;
                dx += d4 * d4;
            }
            if (y + 1 < HH) {
                float4 nxt = sp4[(size_t)(y + 1) * (WW / 4) + tid];
                float e1 = nxt.x - cur.x;
                float e2 = nxt.y - cur.y;
                float e3 = nxt.z - cur.z;
                float e4 = nxt.w - cur.w;
                dy += e1 * e1 + e2 * e2 + e3 * e3 + e4 * e4;
                cur = nxt;
            }
        }
        acc1 = dx; acc2 = dy;
    } else {
        // ---------------- NCC ----------------
        const int w = (bid - SM_BLOCKS) * 8 + (tid >> 5);
        const int s = w % NSTRIP;
        const int r = w / NSTRIP;
        const int v = r % VSEG;
        const int b = r / VSEG;

        const int ca = s * OUTW - 4 + 2 * lane;         // even raw col for this lane
        const bool okA = (unsigned)ca < (unsigned)WW;
        const bool okB = (unsigned)(ca + 1) < (unsigned)WW;
        int cac = ca < 0 ? 0 : (ca > (WW - 2) ? (WW - 2) : ca);

        const float2* Ip = (const float2*)(I + (size_t)b * HH * WW + cac);
        const float2* Jp = (const float2*)(J + (size_t)b * HH * WW + cac);

        const bool lmid  = (lane >= 2) && (lane <= 29);
        const bool maskA = lmid && okA;
        const bool maskB = lmid && okB;
        const int  y0    = v * SEG;

        const bool colclean = __all_sync(0xffffffffu, okA && okB);
        const bool yclean   = (y0 >= 4) && (y0 + SEG + 4 <= HH);

        if (colclean) {
            acc0 = yclean ? ncc_task<false, true >(Ip, Jp, y0, okA, okB, maskA, maskB)
                          : ncc_task<false, false>(Ip, Jp, y0, okA, okB, maskA, maskB);
        } else {
            acc0 = yclean ? ncc_task<true,  true >(Ip, Jp, y0, okA, okB, maskA, maskB)
                          : ncc_task<true,  false>(Ip, Jp, y0, okA, okB, maskA, maskB);
        }
    }

    // ---------------- block reduction + global accumulate ----------------
    const unsigned full = 0xffffffffu;
    #pragma unroll
    for (int off = 16; off; off >>= 1) {
        acc0 += __shfl_down_sync(full, acc0, off);
        acc1 += __shfl_down_sync(full, acc1, off);
        acc2 += __shfl_down_sync(full, acc2, off);
    }
    if (lane == 0) {
        const int wi = tid >> 5;
        red[0][wi] = acc0;
        red[1][wi] = acc1;
        red[2][wi] = acc2;
    }
    __syncthreads();
    if (tid == 0) {
        float a0 = 0.f, a1 = 0.f, a2 = 0.f;
        #pragma unroll
        for (int wi = 0; wi < NT / 32; wi++) {
            a0 += red[0][wi]; a1 += red[1][wi]; a2 += red[2][wi];
        }
        if (bid < SM_BLOCKS) {
            atomicAdd(&g_acc[1], (double)a1);
            atomicAdd(&g_acc[2], (double)a2);
        } else {
            atomicAdd(&g_acc[0], (double)a0);
        }
        __threadfence();
        unsigned old = atomicAdd(&g_count, 1u);
        if (old == TOTAL_BLOCKS - 1) {
            __threadfence();
            volatile double* ga = g_acc;
            double c  = ga[0];
            double xs = ga[1];
            double ys = ga[2];
            double nccl = -c / ((double)BB * HH * WW);
            double mdx  = xs / ((double)BB * 2.0 * HH * (WW - 1));
            double mdy  = ys / ((double)BB * 2.0 * (HH - 1) * WW);
            double sml  = (mdx + mdy) * 0.5 * 0.01;
            out[0] = (float)(nccl + sml);
            out[1] = (float)nccl;
            out[2] = (float)sml;
            // reset for next graph replay
            ga[0] = 0.0; ga[1] = 0.0; ga[2] = 0.0;
            __threadfence();
            atomicExch(&g_count, 0u);
        }
    }
}

extern "C" void kernel_launch(void* const* d_in, const int* in_sizes, int n_in,
                              void* d_out, int out_size)
{
    const float* I = (const float*)d_in[0];
    const float* J = (const float*)d_in[1];
    const float* s = (const float*)d_in[2];
    // d_in[3] = sum_filt (all-ones 9x9) is baked into the math
    float* out = (float*)d_out;

    fused_kernel<<<TOTAL_BLOCKS, NT>>>(I, J, s, out);
}

// round 8
// speedup vs baseline: 1.0875x; 1.0319x over previous
#include <cuda_runtime.h>

#define BB 8
#define HH 1024
#define WW 1024
#define NT 256

// ---- NCC warp tasks: float2-per-lane, I-only register ring ----
#define OUTW 56                        // output cols per warp-row
#define NSTRIP 19                      // ceil(1024/56)
#define SEG 16                         // output rows per warp task
#define VSEG (HH / SEG)                // 64
#define NCC_TASKS (NSTRIP * VSEG * BB) // 9728

// ---- smoothness warp tasks: 16-row x 128-col strip passes ----
#define SM_TASKS 1024                  // 16 planes x 64 strips
#define NTASKS (SM_TASKS + NCC_TASKS)  // 10752

#define GRID_BLOCKS 592                // 4 per SM x 148 SMs -> single wave

__device__ double g_acc[3] = {0.0, 0.0, 0.0};   // [0]=cc, [1]=dx, [2]=dy
__device__ unsigned int g_ticket = 0;
__device__ unsigned int g_count = 0;

__device__ __forceinline__ float frcp(float x) {
    float r;
    asm("rcp.approx.ftz.f32 %0, %1;" : "=f"(r) : "f"(x));
    return r;
}

// Horizontal 9-tap window sums for a lane owning cols (ca, ca+1).
// wA = cols ca-4..ca+4 ; wB = cols ca-3..ca+5. Valid for lanes 2..29.
__device__ __forceinline__ void hwin(float va, float vb, float& wA, float& wB) {
    const unsigned m = 0xffffffffu;
    float P   = va + vb;
    float t1  = P + __shfl_down_sync(m, P, 1);
    float Q   = t1 + __shfl_down_sync(m, t1, 2);
    float Qm2 = __shfl_up_sync(m, Q, 2);
    float Qm1 = __shfl_up_sync(m, Q, 1);
    float ap2 = __shfl_down_sync(m, va, 2);
    float bm2 = __shfl_up_sync(m, vb, 2);
    wA = Qm2 + ap2;
    wB = Qm1 + bm2;
}

template<bool MASKED, bool YCLEAN>
__device__ __forceinline__ float ncc_task(const float2* __restrict__ Ip,
                                          const float2* __restrict__ Jp,
                                          int y0, bool okA, bool okB,
                                          bool maskA, bool maskB)
{
    const int RS = WW / 2;
    const float2 z = make_float2(0.f, 0.f);

    float2 rI[8];   // ring of I rows y-4..y+3 ; slot = (row-(y0-4)) & 7
    float sIa=0,sIb=0,sJa=0,sJb=0,sIIa=0,sIIb=0,sJJa=0,sJJb=0,sIJa=0,sIJb=0;

    #pragma unroll
    for (int k = 0; k < 8; k++) {
        const int y = y0 - 4 + k;
        const bool ok = YCLEAN || (y >= 0);
        float2 vi = ok ? Ip[(long)y * RS] : z;
        float2 vj = ok ? Jp[(long)y * RS] : z;
        if (MASKED) {
            if (!okA) { vi.x = 0.f; vj.x = 0.f; }
            if (!okB) { vi.y = 0.f; vj.y = 0.f; }
        }
        rI[k] = vi;
        sIa += vi.x; sIb += vi.y; sJa += vj.x; sJb += vj.y;
        sIIa = fmaf(vi.x, vi.x, sIIa); sIIb = fmaf(vi.y, vi.y, sIIb);
        sJJa = fmaf(vj.x, vj.x, sJJa); sJJb = fmaf(vj.y, vj.y, sJJb);
        sIJa = fmaf(vi.x, vj.x, sIJa); sIJb = fmaf(vi.y, vj.y, sIJb);
    }

    const float2* pIn = Ip + (long)(y0 + 4) * RS;
    const float2* pJn = Jp + (long)(y0 + 4) * RS;
    const float2* pJo = Jp + (long)(y0 - 4) * RS;
    const int ylim = HH - 4 - y0;

    const float inv81 = 1.0f / 81.0f;
    float ccSum = 0.f;

    for (int blk = 0; blk < SEG / 8; blk++) {
        #pragma unroll
        for (int k = 0; k < 8; k++) {
            const int u = blk * 8 + k;
            float2 iN, jN, jO;
            if (YCLEAN) {
                iN = pIn[(long)u * RS];
                jN = pJn[(long)u * RS];
                jO = pJo[(long)u * RS];
            } else {
                const bool okn = u < ylim;
                const bool oko = (y0 + u - 4) >= 0;
                iN = okn ? pIn[(long)u * RS] : z;
                jN = okn ? pJn[(long)u * RS] : z;
                jO = oko ? pJo[(long)u * RS] : z;
            }
            if (MASKED) {
                if (!okA) { iN.x = 0.f; jN.x = 0.f; jO.x = 0.f; }
                if (!okB) { iN.y = 0.f; jN.y = 0.f; jO.y = 0.f; }
            }
            const float2 iO = rI[k];
            rI[k] = iN;

            // add row y+4 -> window rows y-4..y+4
            sIa += iN.x; sIb += iN.y; sJa += jN.x; sJb += jN.y;
            sIIa = fmaf(iN.x, iN.x, sIIa); sIIb = fmaf(iN.y, iN.y, sIIb);
            sJJa = fmaf(jN.x, jN.x, sJJa); sJJb = fmaf(jN.y, jN.y, sJJb);
            sIJa = fmaf(iN.x, jN.x, sIJa); sIJb = fmaf(iN.y, jN.y, sIJb);

            float TIa,TIb,TJa,TJb,TIIa,TIIb,TJJa,TJJb,TIJa,TIJb;
            hwin(sIa,  sIb,  TIa,  TIb);
            hwin(sJa,  sJb,  TJa,  TJb);
            hwin(sIIa, sIIb, TIIa, TIIb);
            hwin(sJJa, sJJb, TJJa, TJJb);
            hwin(sIJa, sIJb, TIJa, TIJb);

            {   // col A
                float u1 = TIa * inv81;
                float cr = fmaf(-u1, TJa, TIJa);
                float iv = fmaf(-u1, TIa, TIIa);
                float jv = fmaf(-TJa * inv81, TJa, TJJa);
                float cc = cr * cr * frcp(fmaf(iv, jv, 1e-9f));
                if (maskA) ccSum += cc;
            }
            {   // col B
                float u1 = TIb * inv81;
                float cr = fmaf(-u1, TJb, TIJb);
                float iv = fmaf(-u1, TIb, TIIb);
                float jv = fmaf(-TJb * inv81, TJb, TJJb);
                float cc = cr * cr * frcp(fmaf(iv, jv, 1e-9f));
                if (maskB) ccSum += cc;
            }

            // drop row y-4
            sIa -= iO.x; sIb -= iO.y; sJa -= jO.x; sJb -= jO.y;
            sIIa = fmaf(-iO.x, iO.x, sIIa); sIIb = fmaf(-iO.y, iO.y, sIIb);
            sJJa = fmaf(-jO.x, jO.x, sJJa); sJJb = fmaf(-jO.y, jO.y, sJJb);
            sIJa = fmaf(-iO.x, jO.x, sIJa); sIJb = fmaf(-iO.y, jO.y, sIJb);
        }
    }
    return ccSum;
}

__global__ __launch_bounds__(NT, 4)
void fused_kernel(const float* __restrict__ I,
                  const float* __restrict__ J,
                  const float* __restrict__ S,
                  float* __restrict__ out)
{
    __shared__ float red[3][NT / 32];
    const int tid  = threadIdx.x;
    const int lane = tid & 31;
    const unsigned full = 0xffffffffu;

    float acc0 = 0.f, acc1 = 0.f, acc2 = 0.f;

    for (;;) {
        unsigned t;
        if (lane == 0) t = atomicAdd(&g_ticket, 1u);
        t = __shfl_sync(full, t, 0);
        if (t >= NTASKS) break;

        if (t < SM_TASKS) {
            // ------------- smoothness: 16-row strip, 8 col passes -------------
            const int plane = t >> 6;           // /64
            const int strip = t & 63;
            const float*  spf = S + (size_t)plane * HH * WW;
            const float4* sp4 = (const float4*)spf;
            const int y0 = strip * 16;

            #pragma unroll 1
            for (int p = 0; p < 8; p++) {
                const int cidx = p * 32 + lane;          // float4 index in row
                float4 cur = sp4[(size_t)y0 * 256 + cidx];
                #pragma unroll 4
                for (int y = y0; y < y0 + 16; y++) {
                    float d1 = cur.y - cur.x;
                    float d2 = cur.z - cur.y;
                    float d3 = cur.w - cur.z;
                    acc1 += d1 * d1 + d2 * d2 + d3 * d3;
                    if (cidx < 255) {
                        float nx = spf[(size_t)y * WW + cidx * 4 + 4];
                        float d4 = nx - cur.w;
                        acc1 += d4 * d4;
                    }
                    if (y + 1 < HH) {
                        float4 nxt = sp4[(size_t)(y + 1) * 256 + cidx];
                        float e1 = nxt.x - cur.x;
                        float e2 = nxt.y - cur.y;
                        float e3 = nxt.z - cur.z;
                        float e4 = nxt.w - cur.w;
                        acc2 += e1 * e1 + e2 * e2 + e3 * e3 + e4 * e4;
                        cur = nxt;
                    }
                }
            }
        } else {
            // ------------- NCC -------------
            unsigned n = t - SM_TASKS;
            const int s = n % NSTRIP;
            const int r = n / NSTRIP;
            const int v = r % VSEG;
            const int b = r / VSEG;

            const int ca = s * OUTW - 4 + 2 * lane;
            const bool okA = (unsigned)ca < (unsigned)WW;
            const bool okB = (unsigned)(ca + 1) < (unsigned)WW;
            int cac = ca < 0 ? 0 : (ca > (WW - 2) ? (WW - 2) : ca);

            const float2* Ip = (const float2*)(I + (size_t)b * HH * WW + cac);
            const float2* Jp = (const float2*)(J + (size_t)b * HH * WW + cac);

            const bool lmid  = (lane >= 2) && (lane <= 29);
            const bool maskA = lmid && okA;
            const bool maskB = lmid && okB;
            const int  y0    = v * SEG;

            const bool colclean = __all_sync(full, okA && okB);
            const bool yclean   = (y0 >= 4) && (y0 + SEG + 4 <= HH);

            if (colclean) {
                acc0 += yclean ? ncc_task<false, true >(Ip, Jp, y0, okA, okB, maskA, maskB)
                               : ncc_task<false, false>(Ip, Jp, y0, okA, okB, maskA, maskB);
            } else {
                acc0 += yclean ? ncc_task<true,  true >(Ip, Jp, y0, okA, okB, maskA, maskB)
                               : ncc_task<true,  false>(Ip, Jp, y0, okA, okB, maskA, maskB);
            }
        }
    }

    // ---------------- block reduction + global accumulate ----------------
    #pragma unroll
    for (int off = 16; off; off >>= 1) {
        acc0 += __shfl_down_sync(full, acc0, off);
        acc1 += __shfl_down_sync(full, acc1, off);
        acc2 += __shfl_down_sync(full, acc2, off);
    }
    if (lane == 0) {
        const int wi = tid >> 5;
        red[0][wi] = acc0;
        red[1][wi] = acc1;
        red[2][wi] = acc2;
    }
    __syncthreads();
    if (tid == 0) {
        float a0 = 0.f, a1 = 0.f, a2 = 0.f;
        #pragma unroll
        for (int wi = 0; wi < NT / 32; wi++) {
            a0 += red[0][wi]; a1 += red[1][wi]; a2 += red[2][wi];
        }
        atomicAdd(&g_acc[0], (double)a0);
        atomicAdd(&g_acc[1], (double)a1);
        atomicAdd(&g_acc[2], (double)a2);
        __threadfence();
        unsigned old = atomicAdd(&g_count, 1u);
        if (old == GRID_BLOCKS - 1) {
            __threadfence();
            volatile double* ga = g_acc;
            double c  = ga[0];
            double xs = ga[1];
            double ys = ga[2];
            double nccl = -c / ((double)BB * HH * WW);
            double mdx  = xs / ((double)BB * 2.0 * HH * (WW - 1));
            double mdy  = ys / ((double)BB * 2.0 * (HH - 1) * WW);
            double sml  = (mdx + mdy) * 0.5 * 0.01;
            out[0] = (float)(nccl + sml);
            out[1] = (float)nccl;
            out[2] = (float)sml;
            // reset for next graph replay
            ga[0] = 0.0; ga[1] = 0.0; ga[2] = 0.0;
            atomicExch(&g_ticket, 0u);
            __threadfence();
            atomicExch(&g_count, 0u);
        }
    }
}

extern "C" void kernel_launch(void* const* d_in, const int* in_sizes, int n_in,
                              void* d_out, int out_size)
{
    const float* I = (const float*)d_in[0];
    const float* J = (const float*)d_in[1];
    const float* s = (const float*)d_in[2];
    // d_in[3] = sum_filt (all-ones 9x9) is baked into the math
    float* out = (float*)d_out;

    fused_kernel<<<GRID_BLOCKS, NT>>>(I, J, s, out);
}